// round 2
// baseline (speedup 1.0000x reference)
#include <cuda_runtime.h>
#include <cuda_bf16.h>
#include <cstdint>

// Problem constants
#define NUM_QT   65
#define NUM_OT   151
#define PAIR_NUM 90
#define BATCH    8192
#define BOX      10
#define TOTAL_ELEMS (NUM_QT * PAIR_NUM * NUM_OT * NUM_OT)  // 133,385,850

// ---------------------------------------------------------------------------
// Kernel 1: vectorized copy score_matrix -> out (float4 bulk + scalar tail)
// ---------------------------------------------------------------------------
__global__ void copy_kernel(const float4* __restrict__ src4,
                            float4* __restrict__ dst4,
                            const float* __restrict__ src,
                            float* __restrict__ dst,
                            int n4, int n)
{
    int stride = gridDim.x * blockDim.x;
    for (int i = blockIdx.x * blockDim.x + threadIdx.x; i < n4; i += stride) {
        dst4[i] = src4[i];
    }
    // tail (n - n4*4 elements, at most 3)
    int tail_start = n4 * 4;
    int t = blockIdx.x * blockDim.x + threadIdx.x;
    int tail_n = n - tail_start;
    if (t < tail_n) {
        dst[tail_start + t] = src[tail_start + t];
    }
}

// ---------------------------------------------------------------------------
// Kernel 2: scatter-add attention products.
// One thread per (batch, pair). pair p -> i = p/9, j' = p%9, j = j' + (j' >= i).
// out[qt[b]][p][obj_label[b,j]][obj_label[b,i]] += att[b,i]*att[b,j]
// ---------------------------------------------------------------------------
__global__ void scatter_kernel(const int* __restrict__ obj_label,
                               const int* __restrict__ qus_type,
                               const float* __restrict__ attention,
                               float* __restrict__ out)
{
    int idx = blockIdx.x * blockDim.x + threadIdx.x;
    if (idx >= BATCH * PAIR_NUM) return;

    int b = idx / PAIR_NUM;
    int p = idx - b * PAIR_NUM;
    int i = p / (BOX - 1);
    int jr = p - i * (BOX - 1);
    int j = jr + (jr >= i ? 1 : 0);

    int qt  = __ldg(&qus_type[b]);
    int oli = __ldg(&obj_label[b * BOX + i]);
    int olj = __ldg(&obj_label[b * BOX + j]);
    float ai = __ldg(&attention[b * BOX + i]);
    float aj = __ldg(&attention[b * BOX + j]);

    // offset = ((qt*PAIR + p)*NUM_OT + ol1)*NUM_OT + ol2, ol1=label[j], ol2=label[i]
    long long off = ((long long)(qt * PAIR_NUM + p) * NUM_OT + olj) * NUM_OT + oli;
    atomicAdd(out + off, ai * aj);
}

// ---------------------------------------------------------------------------
// Launch
// Inputs (metadata order matching setup_inputs):
//   d_in[0] = obj_label  int32  [8192,10]
//   d_in[1] = qus_type   int32  [8192]
//   d_in[2] = attention  float32[8192,10]
//   d_in[3] = score_matrix float32 [65,90,151,151]
// ---------------------------------------------------------------------------
extern "C" void kernel_launch(void* const* d_in, const int* in_sizes, int n_in,
                              void* d_out, int out_size)
{
    const int*   obj_label = (const int*)d_in[0];
    const int*   qus_type  = (const int*)d_in[1];
    const float* attention = (const float*)d_in[2];
    const float* score     = (const float*)d_in[3];
    float*       out       = (float*)d_out;

    const int n  = TOTAL_ELEMS;
    const int n4 = n / 4;

    // Copy: saturate DRAM. 148 SMs * ~16 blocks/SM worth of work via grid-stride.
    {
        int threads = 256;
        int blocks = 148 * 16;
        copy_kernel<<<blocks, threads>>>((const float4*)score, (float4*)out,
                                         score, out, n4, n);
    }

    // Scatter
    {
        int total = BATCH * PAIR_NUM;  // 737,280
        int threads = 256;
        int blocks = (total + threads - 1) / threads;
        scatter_kernel<<<blocks, threads>>>(obj_label, qus_type, attention, out);
    }
}